// round 8
// baseline (speedup 1.0000x reference)
#include <cuda_runtime.h>
#include <cuda_bf16.h>
#include <cstdint>

// Problem constants
#define B_   8
#define C_   64
#define N_   4096
#define K_   20
#define M_   8
#define OUTC 64
#define CM   (C_ * M_)      // 512
#define P_   (B_ * N_)      // 32768 points
#define NEG_SLOPE 0.2f

// Scratch (allocation-free: __device__ globals)
__device__ float g_ft[(size_t)B_ * N_ * C_];        // feature transposed (B,N,C)  8 MB
__device__ float g_agg[(size_t)P_ * CM];            // per-point agg vectors       64 MB

// ---------------------------------------------------------------------------
// Kernel 1: transpose feature (B,C,N) -> ft (B,N,C)
// ---------------------------------------------------------------------------
__global__ void k_transpose(const float* __restrict__ feature) {
    __shared__ float tile[32][33];
    int b  = blockIdx.z;
    int c0 = blockIdx.y * 32;
    int n0 = blockIdx.x * 32;
    int tx = threadIdx.x;          // 0..31
    int ty = threadIdx.y;          // 0..7

    const float* src = feature + ((size_t)b * C_) * N_;
#pragma unroll
    for (int i = 0; i < 32; i += 8) {
        tile[ty + i][tx] = src[(size_t)(c0 + ty + i) * N_ + (n0 + tx)];
    }
    __syncthreads();
    float* dst = g_ft + ((size_t)b * N_) * C_;
#pragma unroll
    for (int i = 0; i < 32; i += 8) {
        dst[(size_t)(n0 + ty + i) * C_ + (c0 + tx)] = tile[tx][ty + i];
    }
}

// ---------------------------------------------------------------------------
// Kernel 2: per-point perm matrix + softmax + feature aggregation.
// 128 threads per block, 2 points per block.  Within a point's 64-thread
// group, thread (t & 63) == channel c in the aggregation phase.
// NOTE: neigh_indexs is int32 on device (JAX default x64-disabled).
// ---------------------------------------------------------------------------
__global__ __launch_bounds__(128) void k_agg(const float* __restrict__ x,
                                             const int* __restrict__ nbr,
                                             const float* __restrict__ kern) {
    int t  = threadIdx.x;          // 0..127
    int q  = t >> 6;               // local point 0/1
    int tq = t & 63;               // lane within point group
    int p  = blockIdx.x * 2 + q;   // global point
    int b  = p >> 12;              // / 4096

    __shared__ float px[2][K_][3];
    __shared__ int   sidx[2][K_];
    __shared__ float perm[2][K_][M_];
    __shared__ float skern[3 * M_];

    if (t < 3 * M_) skern[t] = kern[t];
    if (tq < K_) {
        int ii = nbr[(size_t)p * K_ + tq];
        sidx[q][tq] = ii;
        const float* xb = x + (size_t)b * 3 * N_;
        px[q][tq][0] = xb[ii];
        px[q][tq][1] = xb[N_ + ii];
        px[q][tq][2] = xb[2 * N_ + ii];
    }
    __syncthreads();

    if (tq < K_) {
        float r0 = px[q][tq][0] - px[q][0][0];
        float r1 = px[q][tq][1] - px[q][0][1];
        float r2 = px[q][tq][2] - px[q][0][2];
#pragma unroll
        for (int m = 0; m < M_; m++) {
            float v = r0 * skern[m] + r1 * skern[M_ + m] + r2 * skern[2 * M_ + m];
            if (tq == 0 && m == 0) v += 1.0f;
            perm[q][tq][m] = v;
        }
    }
    __syncthreads();

    // softmax over k (axis 2) for each column m
    if (tq < M_) {
        float mx = -1e30f;
#pragma unroll
        for (int k = 0; k < K_; k++) mx = fmaxf(mx, perm[q][k][tq]);
        float s = 0.0f;
#pragma unroll
        for (int k = 0; k < K_; k++) {
            float e = __expf(perm[q][k][tq] - mx);
            perm[q][k][tq] = e;
            s += e;
        }
        float inv = 1.0f / s;
#pragma unroll
        for (int k = 0; k < K_; k++) perm[q][k][tq] *= inv;
    }
    __syncthreads();

    // tq == channel c ; gather 20 neighbor features, accumulate agg[c][m]
    float acc[M_];
#pragma unroll
    for (int m = 0; m < M_; m++) acc[m] = 0.0f;

    const float* ftb = g_ft + ((size_t)b * N_) * C_;
#pragma unroll
    for (int k = 0; k < K_; k++) {
        float f = ftb[(size_t)sidx[q][k] * C_ + tq];
#pragma unroll
        for (int m = 0; m < M_; m++) acc[m] = fmaf(f, perm[q][k][m], acc[m]);
    }

    float* outp = g_agg + (size_t)p * CM + tq * M_;
    *(float4*)(outp)     = make_float4(acc[0], acc[1], acc[2], acc[3]);
    *(float4*)(outp + 4) = make_float4(acc[4], acc[5], acc[6], acc[7]);
}

// ---------------------------------------------------------------------------
// Kernel 3: GEMM  out[p][oc] = sum_j agg[p][j] * W[oc][j]  + epilogue
//   BM=128 points per block, all 64 oc, BK=32.  256 threads, 8x4 micro-tiles
//   with interleaved mapping (p = p0 + tx + 16*i, oc = ty + 16*j) so every
//   shared read is consecutive-lane conflict-free.  float4 staging.
//   Epilogue: + bias, leaky_relu(0.2), + feature residual, store (B,OUTC,N)
// ---------------------------------------------------------------------------
#define BM 128
#define BK 32
#define BMP (BM + 1)     // 129: staging-store stride conflict-free

__global__ __launch_bounds__(256) void k_gemm(const float* __restrict__ w,
                                              const float* __restrict__ bias,
                                              const float* __restrict__ feature,
                                              float* __restrict__ out) {
    int p0  = blockIdx.x * BM;
    int tid = threadIdx.x;
    int tx  = tid & 15;            // point group:   p  = p0 + tx + 16*i
    int ty  = tid >> 4;            // oc group:      oc = ty + 16*j

    __shared__ float As[BK][BMP];        // k-major
    __shared__ float Ws[BK][OUTC + 1];

    float acc[8][4];
#pragma unroll
    for (int i = 0; i < 8; i++)
#pragma unroll
        for (int j = 0; j < 4; j++) acc[i][j] = 0.0f;

    for (int k0 = 0; k0 < CM; k0 += BK) {
        // Stage A: 128 rows (points) x 32 k as float4 units.
        // 128 rows * 8 quads = 1024 units, 256 threads -> 4 units each.
#pragma unroll
        for (int r = 0; r < 4; r++) {
            int u   = r * 256 + tid;
            int row = u >> 3;            // 0..127
            int kq  = u & 7;             // k-quad 0..7
            float4 v = *(const float4*)(g_agg + (size_t)(p0 + row) * CM + k0 + kq * 4);
            As[kq * 4 + 0][row] = v.x;
            As[kq * 4 + 1][row] = v.y;
            As[kq * 4 + 2][row] = v.z;
            As[kq * 4 + 3][row] = v.w;
        }
        // Stage W: 64 rows (oc) x 32 k as float4 units -> 2 units each.
#pragma unroll
        for (int r = 0; r < 2; r++) {
            int u  = r * 256 + tid;
            int oc = u >> 3;             // 0..63
            int kq = u & 7;
            float4 v = *(const float4*)(w + (size_t)oc * CM + k0 + kq * 4);
            Ws[kq * 4 + 0][oc] = v.x;
            Ws[kq * 4 + 1][oc] = v.y;
            Ws[kq * 4 + 2][oc] = v.z;
            Ws[kq * 4 + 3][oc] = v.w;
        }
        __syncthreads();

#pragma unroll
        for (int kk = 0; kk < BK; kk++) {
            float a[8], wv[4];
#pragma unroll
            for (int i = 0; i < 8; i++) a[i]  = As[kk][tx + 16 * i];
#pragma unroll
            for (int j = 0; j < 4; j++) wv[j] = Ws[kk][ty + 16 * j];
#pragma unroll
            for (int i = 0; i < 8; i++)
#pragma unroll
                for (int j = 0; j < 4; j++)
                    acc[i][j] = fmaf(a[i], wv[j], acc[i][j]);
        }
        __syncthreads();
    }

    // Epilogue.  128-point tile never crosses a batch boundary (4096 % 128 == 0).
    int b  = p0 >> 12;
    int nb = (p0 & (N_ - 1)) + tx;
#pragma unroll
    for (int j = 0; j < 4; j++) {
        int oc   = ty + 16 * j;
        float bi = bias[oc];
        const float* fptr = feature + ((size_t)b * C_ + oc) * N_;
        float*       optr = out     + ((size_t)b * OUTC + oc) * N_;
#pragma unroll
        for (int i = 0; i < 8; i++) {
            int n = nb + 16 * i;
            float tv = acc[i][j] + bi;
            tv = tv > 0.0f ? tv : NEG_SLOPE * tv;
            optr[n] = tv + fptr[n];
        }
    }
}

// ---------------------------------------------------------------------------
// Launch
// ---------------------------------------------------------------------------
extern "C" void kernel_launch(void* const* d_in, const int* in_sizes, int n_in,
                              void* d_out, int out_size) {
    const float* x      = (const float*)d_in[0];       // (B,3,N)
    const float* feat   = (const float*)d_in[1];       // (B,C,N)
    const int*   nbr    = (const int*)d_in[2];         // (B,N,K) int32 on device
    const float* kern   = (const float*)d_in[3];       // (3,M)
    const float* conv_w = (const float*)d_in[4];       // (OUTC, C*M)
    const float* conv_b = (const float*)d_in[5];       // (OUTC,)
    float*       out    = (float*)d_out;               // (B,OUTC,N)

    // K1: transpose feature -> g_ft
    dim3 tb(32, 8);
    dim3 tg(N_ / 32, C_ / 32, B_);
    k_transpose<<<tg, tb>>>(feat);

    // K2: per-point aggregation -> g_agg   (2 points / block)
    k_agg<<<P_ / 2, 128>>>(x, nbr, kern);

    // K3: GEMM + epilogue -> out
    k_gemm<<<P_ / BM, 256>>>(conv_w, conv_b, feat, out);
}